// round 14
// baseline (speedup 1.0000x reference)
#include <cuda_runtime.h>
#include <cuda_bf16.h>
#include <stdint.h>

// RoIAlign: feat (B=4, C=256, H=200, W=304) fp32, rois (N,5) fp32
// OUT=7, SCALE=0.25, sampling_ratio=1, aligned=False
// out: (N, C, 7, 7) fp32

#define B_ 4
#define C_ 256
#define H_ 200
#define W_ 304
#define OUT_ 7
#define BINS_PER_ROI (OUT_ * OUT_)      // 49
#define HW_ (H_ * W_)                   // 60800
#define CHW_ (C_ * HW_)                 // 15,564,800
#define SCALE_ 0.25f

#define MAX_ROWS 14                     // 7 (y0,y0+1) pairs max
#define TILE_XS 57                      // x stride: max span 55, odd for banks
#define CH_PER_BLOCK 8
#define NCG_ (C_ / CH_PER_BLOCK)        // 32 channel groups
#define ELEMS_ (CH_PER_BLOCK * BINS_PER_ROI)  // 392

#define MAX_ROIS 8192
__device__ float4 g_w[MAX_ROIS * BINS_PER_ROI];     // bilinear weights * valid
__device__ int    g_toff[MAX_ROIS * BINS_PER_ROI];  // smem tap offset r0*57+xoff
__device__ int    g_rowlist[MAX_ROIS * 16];         // unique feature rows (y)
__device__ int4   g_meta[MAX_ROIS];                 // {xmin, span, nrows, b*CHW}
__device__ int    g_order[MAX_ROIS];                // rois sorted by batch

__device__ __forceinline__ int calc_y0(float sy1, float bin_h, int ph) {
    float y = sy1 + ((float)ph + 0.5f) * bin_h;
    y = fminf(fmaxf(y, 0.0f), (float)(H_ - 1));
    int y0 = (int)floorf(y);
    if (y0 >= H_ - 1) y0 = H_ - 2;
    return y0;
}
__device__ __forceinline__ int calc_x0(float sx1, float bin_w, int pw) {
    float x = sx1 + ((float)pw + 0.5f) * bin_w;
    x = fminf(fmaxf(x, 0.0f), (float)(W_ - 1));
    int x0 = (int)floorf(x);
    if (x0 >= W_ - 1) x0 = W_ - 2;
    return x0;
}

// ---------------------------------------------------------------------------
// Fused phase 1: blocks [0, gridDim-2] do per-(roi,bin) prep; last block does
// the 4-bucket batch counting sort (disjoint outputs; gather needs both).
// ---------------------------------------------------------------------------
__global__ __launch_bounds__(256)
void roi_prep_sort_kernel(const float* __restrict__ rois,
                          int n_bins, int n_rois) {
    int tid = threadIdx.x;

    if (blockIdx.x == gridDim.x - 1) {
        __shared__ int s_count[B_];
        __shared__ int s_base[B_];
        __shared__ int s_pos[B_];

        if (tid < B_) s_count[tid] = 0;
        __syncthreads();
        for (int n = tid; n < n_rois; n += 256)
            atomicAdd(&s_count[(int)rois[n * 5]], 1);
        __syncthreads();
        if (tid == 0) {
            int acc = 0;
            for (int b = 0; b < B_; b++) { s_base[b] = acc; acc += s_count[b]; s_pos[b] = 0; }
        }
        __syncthreads();
        for (int n = tid; n < n_rois; n += 256) {
            int b = (int)rois[n * 5];
            int pos = s_base[b] + atomicAdd(&s_pos[b], 1);
            g_order[pos] = n;
        }
        return;
    }

    int i = blockIdx.x * 256 + tid;
    if (i >= n_bins) return;

    int n  = i / BINS_PER_ROI;
    int p  = i - n * BINS_PER_ROI;
    int ph = p / OUT_;
    int pw = p - ph * OUT_;

    const float* r = rois + n * 5;
    int   b   = (int)r[0];
    float sx1 = r[1] * SCALE_;
    float sy1 = r[2] * SCALE_;
    float sx2 = r[3] * SCALE_;
    float sy2 = r[4] * SCALE_;

    float rw = fmaxf(sx2 - sx1, 1.0f);   // aligned=False -> clamp to 1
    float rh = fmaxf(sy2 - sy1, 1.0f);
    float bin_w = rw * (1.0f / OUT_);
    float bin_h = rh * (1.0f / OUT_);

    // ---- own sample point: weights ----
    float x = sx1 + ((float)pw + 0.5f) * bin_w;
    float y = sy1 + ((float)ph + 0.5f) * bin_h;
    float valid = (y > -1.0f && y < (float)H_ && x > -1.0f && x < (float)W_)
                      ? 1.0f : 0.0f;
    y = fminf(fmaxf(y, 0.0f), (float)(H_ - 1));
    x = fminf(fmaxf(x, 0.0f), (float)(W_ - 1));
    int   y0 = (int)floorf(y);
    int   x0 = (int)floorf(x);
    float ly = y - (float)y0;
    float lx = x - (float)x0;
    if (y0 >= H_ - 1) { y0 = H_ - 2; ly = 1.0f; }
    if (x0 >= W_ - 1) { x0 = W_ - 2; lx = 1.0f; }
    float hy = 1.0f - ly;
    float hx = 1.0f - lx;

    g_w[i] = make_float4(hy * hx * valid, hy * lx * valid,
                         ly * hx * valid, ly * lx * valid);

    // ---- row index of y0 in the roi's sorted-unique row list ----
    // List = append-unique of {y0(j), y0(j)+1} for j=0..6 (monotone in j).
    int rows[MAX_ROWS];
    int nr = 0, last = -1000000;
    #pragma unroll
    for (int j = 0; j < OUT_; j++) {
        int v = calc_y0(sy1, bin_h, j);
        if (v > last)     { rows[nr++] = v;     last = v; }
        if (v + 1 > last) { rows[nr++] = v + 1; last = v + 1; }
    }
    int r0idx = 0;
    #pragma unroll
    for (int k = 0; k < MAX_ROWS; k++)
        if (k < nr && rows[k] < y0) r0idx++;

    int xmin = calc_x0(sx1, bin_w, 0);
    g_toff[i] = r0idx * TILE_XS + (x0 - xmin);

    // ---- per-roi metadata (one thread per roi) ----
    if (p == 0) {
        int xmax0 = calc_x0(sx1, bin_w, OUT_ - 1);
        int span  = xmax0 - xmin + 2;          // covers x0..x0+1 of all bins
        for (int k = 0; k < nr; k++) g_rowlist[n * 16 + k] = rows[k];
        g_meta[n] = make_int4(xmin, span, nr, b * CHW_);
    }
}

// ---------------------------------------------------------------------------
// Phase 2: one block = (batch-sorted roi slot, 8-channel group), 256 threads.
// Warp w stages channel c0+w's needed rows into smem with COALESCED loads
// (lanes = consecutive x -> 1-2 lines per warp instruction, vs ~10 for the
// scattered per-bin taps). Compute then takes 4 taps from smem where the
// cost is conflict degree (~1-2), not line count. Base + {0,1,57,58} gives
// all 4 taps from one offset (r1 = r0+1 is guaranteed adjacent in the list).
// ---------------------------------------------------------------------------
__global__ __launch_bounds__(256)
void roi_gather_kernel(const float* __restrict__ feat,
                       float* __restrict__ out) {
    __shared__ float s_tile[CH_PER_BLOCK][MAX_ROWS * TILE_XS];  // 25.5 KB
    __shared__ int   s_rows[MAX_ROWS];

    int slot = blockIdx.x >> 5;          // / NCG_ (32)
    int cg   = blockIdx.x & (NCG_ - 1);
    int n    = g_order[slot];
    int c0   = cg * CH_PER_BLOCK;

    int tid  = threadIdx.x;
    int wid  = tid >> 5;
    int lane = tid & 31;

    int4 meta = g_meta[n];               // {xmin, span, nrows, bbase}
    if (tid < meta.z) s_rows[tid] = g_rowlist[n * 16 + tid];
    __syncthreads();

    // stage: warp w -> channel c0+w
    {
        const float* src = feat + meta.w + (c0 + wid) * HW_ + meta.x;
        float* dst = s_tile[wid];
        for (int rr = 0; rr < meta.z; rr++) {
            const float* rowp = src + s_rows[rr] * W_;
            for (int xx = lane; xx < meta.y; xx += 32)
                dst[rr * TILE_XS + xx] = __ldg(rowp + xx);
        }
    }
    __syncthreads();

    // compute 392 elems; stores contiguous (e is the output offset)
    float* out_base = out + (n * C_ + c0) * BINS_PER_ROI;
    const float4* wbase = g_w + n * BINS_PER_ROI;
    const int*    tbase = g_toff + n * BINS_PER_ROI;

    #pragma unroll
    for (int e = tid; e < ELEMS_; e += 256) {
        int c = e / BINS_PER_ROI;
        int p = e - c * BINS_PER_ROI;

        float4 w    = __ldg(wbase + p);
        int    toff = __ldg(tbase + p);

        const float* tp = s_tile[c] + toff;
        out_base[e] = tp[0] * w.x + tp[1] * w.y
                    + tp[TILE_XS] * w.z + tp[TILE_XS + 1] * w.w;
    }
}

// ---------------------------------------------------------------------------
extern "C" void kernel_launch(void* const* d_in, const int* in_sizes, int n_in,
                              void* d_out, int out_size) {
    const float* feat = (const float*)d_in[0];
    const float* rois = (const float*)d_in[1];
    float* out = (float*)d_out;

    int N = in_sizes[1] / 5;
    int n_bins = N * BINS_PER_ROI;
    int prep_blocks = (n_bins + 255) / 256;

    roi_prep_sort_kernel<<<prep_blocks + 1, 256>>>(rois, n_bins, N);
    roi_gather_kernel<<<N * NCG_, 256>>>(feat, out);
}

// round 15
// speedup vs baseline: 3.5492x; 3.5492x over previous
#include <cuda_runtime.h>
#include <cuda_bf16.h>
#include <stdint.h>

// RoIAlign: feat (B=4, C=256, H=200, W=304) fp32, rois (N,5) fp32
// OUT=7, SCALE=0.25, sampling_ratio=1, aligned=False
// out: (N, C, 7, 7) fp32

#define B_ 4
#define C_ 256
#define H_ 200
#define W_ 304
#define OUT_ 7
#define BINS_PER_ROI (OUT_ * OUT_)      // 49
#define HW_ (H_ * W_)                   // 60800  (== 0 mod 4)
#define CHW_ (C_ * HW_)                 // 15,564,800 (== 0 mod 4)
#define SCALE_ 0.25f

#define CG_ 32                          // channels per gather block
#define NCG_ (C_ / CG_)                 // 8 channel groups
#define GATHER_THREADS 196              // 4 groups x 49 bins
#define CH_PER_THREAD 8                 // 196*8 = 1568 = 32*49 exactly

#define MAX_ROIS 8192
// Per-bin metadata; weights pre-rotated into float4-aligned dot masks.
__device__ int    g_off[MAX_ROIS * BINS_PER_ROI];   // b*CHW + y0*W + x0
__device__ float4 g_wa[MAX_ROIS * BINS_PER_ROI];    // row y0 dot-mask
__device__ float4 g_wb[MAX_ROIS * BINS_PER_ROI];    // row y0+1 dot-mask
__device__ float2 g_we[MAX_ROIS * BINS_PER_ROI];    // (x0&3)==3 spill weights
__device__ int    g_order[MAX_ROIS];                // rois sorted by batch

// ---------------------------------------------------------------------------
// Fused phase 1: blocks [0, gridDim-2] = per-(roi,bin) prep; last block =
// 4-bucket batch counting sort (disjoint outputs; gather depends on both).
// ---------------------------------------------------------------------------
__global__ __launch_bounds__(256)
void roi_prep_sort_kernel(const float* __restrict__ rois,
                          int n_bins, int n_rois) {
    int tid = threadIdx.x;

    if (blockIdx.x == gridDim.x - 1) {
        // sort (order within bucket irrelevant: each roi writes a disjoint
        // output slice, so atomic scatter is deterministic-output-safe)
        __shared__ int s_count[B_];
        __shared__ int s_base[B_];
        __shared__ int s_pos[B_];

        if (tid < B_) s_count[tid] = 0;
        __syncthreads();
        for (int n = tid; n < n_rois; n += 256)
            atomicAdd(&s_count[(int)rois[n * 5]], 1);
        __syncthreads();
        if (tid == 0) {
            int acc = 0;
            for (int b = 0; b < B_; b++) { s_base[b] = acc; acc += s_count[b]; s_pos[b] = 0; }
        }
        __syncthreads();
        for (int n = tid; n < n_rois; n += 256) {
            int b = (int)rois[n * 5];
            int pos = s_base[b] + atomicAdd(&s_pos[b], 1);
            g_order[pos] = n;
        }
        return;
    }

    int i = blockIdx.x * 256 + tid;
    if (i >= n_bins) return;

    int n  = i / BINS_PER_ROI;
    int p  = i - n * BINS_PER_ROI;
    int ph = p / OUT_;
    int pw = p - ph * OUT_;

    const float* r = rois + n * 5;
    int   b   = (int)r[0];
    float sx1 = r[1] * SCALE_;
    float sy1 = r[2] * SCALE_;
    float sx2 = r[3] * SCALE_;
    float sy2 = r[4] * SCALE_;

    float rw = fmaxf(sx2 - sx1, 1.0f);   // aligned=False -> clamp to 1
    float rh = fmaxf(sy2 - sy1, 1.0f);
    float bin_w = rw * (1.0f / OUT_);
    float bin_h = rh * (1.0f / OUT_);

    // sampling_ratio = 1: single sample at bin center
    float x = sx1 + ((float)pw + 0.5f) * bin_w;
    float y = sy1 + ((float)ph + 0.5f) * bin_h;

    float valid = (y > -1.0f && y < (float)H_ && x > -1.0f && x < (float)W_)
                      ? 1.0f : 0.0f;

    y = fminf(fmaxf(y, 0.0f), (float)(H_ - 1));
    x = fminf(fmaxf(x, 0.0f), (float)(W_ - 1));

    int   y0 = (int)floorf(y);
    int   x0 = (int)floorf(x);
    float ly = y - (float)y0;
    float lx = x - (float)x0;

    // Edge re-parameterization: keep (y0+1, x0+1) taps in-bounds.
    if (y0 >= H_ - 1) { y0 = H_ - 2; ly = 1.0f; }
    if (x0 >= W_ - 1) { x0 = W_ - 2; lx = 1.0f; }

    float hy = 1.0f - ly;
    float hx = 1.0f - lx;

    float hyhx = hy * hx * valid;
    float hylx = hy * lx * valid;
    float lyhx = ly * hx * valid;
    float lylx = ly * lx * valid;

    // Rotate weights into float4-aligned dot masks. rslot = x0 & 3: tap x0
    // lands in slot rslot of the aligned float4; x0+1 in rslot+1, spilling
    // to extra scalars when rslot == 3.
    int rslot = x0 & 3;
    float4 wa = make_float4(0.f, 0.f, 0.f, 0.f);
    float4 wb = make_float4(0.f, 0.f, 0.f, 0.f);
    float2 we = make_float2(0.f, 0.f);
    switch (rslot) {
        case 0: wa.x = hyhx; wa.y = hylx; wb.x = lyhx; wb.y = lylx; break;
        case 1: wa.y = hyhx; wa.z = hylx; wb.y = lyhx; wb.z = lylx; break;
        case 2: wa.z = hyhx; wa.w = hylx; wb.z = lyhx; wb.w = lylx; break;
        default: wa.w = hyhx; wb.w = lyhx; we.x = hylx; we.y = lylx; break;
    }

    g_off[i] = b * CHW_ + y0 * W_ + x0;
    g_wa[i]  = wa;
    g_wb[i]  = wb;
    g_we[i]  = we;
}

// ---------------------------------------------------------------------------
// Phase 2: one block = (batch-sorted roi slot, 32-channel group).
// 196 threads = 4 groups x 49 bins; each thread owns ONE bin, metadata in
// registers (loaded once for 8 channels). Per channel: 2x LDG.128 cover
// both tap rows (aligned float4 at off&~3 is always in-bounds since W, HW,
// CHW are multiples of 4), + 25%-of-threads predicated 2-scalar spill,
// + 1 coalesced store. No shared memory, no syncs in the hot path.
// vs R12: warp tap-instructions per element 4 -> ~2.5, same lines/instr.
// ---------------------------------------------------------------------------
__global__ __launch_bounds__(GATHER_THREADS)
void roi_gather_kernel(const float* __restrict__ feat,
                       float* __restrict__ out) {
    int slot = blockIdx.x >> 3;          // / NCG_ (8)
    int cg   = blockIdx.x & (NCG_ - 1);
    int n    = g_order[slot];
    int c0   = cg * CG_;

    int t = threadIdx.x;
    int g = t / BINS_PER_ROI;            // 0..3
    int p = t - g * BINS_PER_ROI;        // 0..48

    int bin = n * BINS_PER_ROI + p;
    int    off = g_off[bin] + (c0 + g * CH_PER_THREAD) * HW_;
    float4 wa  = g_wa[bin];
    float4 wb  = g_wb[bin];
    float2 we  = g_we[bin];

    bool spill = (off & 3) == 3;         // channel-invariant (HW_ % 4 == 0)
    const float4* base = (const float4*)(feat + (off & ~3));

    float* out_base = out + (n * C_ + c0 + g * CH_PER_THREAD) * BINS_PER_ROI + p;

    #pragma unroll
    for (int i = 0; i < CH_PER_THREAD; i++) {
        float4 t0 = __ldg(base + i * (HW_ / 4));
        float4 t1 = __ldg(base + i * (HW_ / 4) + (W_ / 4));

        float acc = t0.x * wa.x + t0.y * wa.y + t0.z * wa.z + t0.w * wa.w
                  + t1.x * wb.x + t1.y * wb.y + t1.z * wb.z + t1.w * wb.w;

        if (spill) {
            const float* pp = feat + off + i * HW_ + 1;
            acc += __ldg(pp) * we.x + __ldg(pp + W_) * we.y;
        }

        out_base[i * BINS_PER_ROI] = acc;
    }
}

// ---------------------------------------------------------------------------
extern "C" void kernel_launch(void* const* d_in, const int* in_sizes, int n_in,
                              void* d_out, int out_size) {
    const float* feat = (const float*)d_in[0];
    const float* rois = (const float*)d_in[1];
    float* out = (float*)d_out;

    int N = in_sizes[1] / 5;
    int n_bins = N * BINS_PER_ROI;
    int prep_blocks = (n_bins + 255) / 256;

    roi_prep_sort_kernel<<<prep_blocks + 1, 256>>>(rois, n_bins, N);
    roi_gather_kernel<<<N * NCG_, GATHER_THREADS>>>(feat, out);
}

// round 16
// speedup vs baseline: 4.1125x; 1.1587x over previous
#include <cuda_runtime.h>
#include <cuda_bf16.h>
#include <stdint.h>

// RoIAlign: feat (B=4, C=256, H=200, W=304) fp32, rois (N,5) fp32
// OUT=7, SCALE=0.25, sampling_ratio=1, aligned=False
// out: (N, C, 7, 7) fp32

#define B_ 4
#define C_ 256
#define H_ 200
#define W_ 304
#define OUT_ 7
#define BINS_PER_ROI (OUT_ * OUT_)      // 49
#define HW_ (H_ * W_)                   // 60800
#define CHW_ (C_ * HW_)                 // 15,564,800
#define SCALE_ 0.25f

#define CG_ 64                          // channels per gather block
#define NCG_ (C_ / CG_)                 // 4 channel groups
#define GATHER_THREADS 196              // 4 subgroups x 49 bins
#define CH_PER_THREAD 16                // 196*16 = 3136 = 64*49 exactly

#define MAX_ROIS 8192
__device__ int    g_off[MAX_ROIS * BINS_PER_ROI];   // b*CHW + y0*W + x0
__device__ float4 g_w[MAX_ROIS * BINS_PER_ROI];     // bilinear weights * valid
__device__ int    g_order[MAX_ROIS];                // rois sorted by batch

// ---------------------------------------------------------------------------
// Fused phase 1: blocks [0, gridDim-2] do per-(roi,bin) prep; the last block
// does a 4-bucket counting sort of rois by batch id (concurrent: disjoint
// outputs; gather depends on both).
// ---------------------------------------------------------------------------
__global__ __launch_bounds__(256)
void roi_prep_sort_kernel(const float* __restrict__ rois,
                          int n_bins, int n_rois) {
    int tid = threadIdx.x;

    if (blockIdx.x == gridDim.x - 1) {
        // ---- sort path (order within bucket irrelevant: each roi writes a
        // disjoint output slice, so atomic scatter is deterministic-safe) ----
        __shared__ int s_count[B_];
        __shared__ int s_base[B_];
        __shared__ int s_pos[B_];

        if (tid < B_) s_count[tid] = 0;
        __syncthreads();

        for (int n = tid; n < n_rois; n += 256)
            atomicAdd(&s_count[(int)rois[n * 5]], 1);
        __syncthreads();

        if (tid == 0) {
            int acc = 0;
            for (int b = 0; b < B_; b++) { s_base[b] = acc; acc += s_count[b]; s_pos[b] = 0; }
        }
        __syncthreads();

        for (int n = tid; n < n_rois; n += 256) {
            int b = (int)rois[n * 5];
            int pos = s_base[b] + atomicAdd(&s_pos[b], 1);
            g_order[pos] = n;
        }
        return;
    }

    // ---- prep path ----
    int i = blockIdx.x * 256 + tid;
    if (i >= n_bins) return;

    int n  = i / BINS_PER_ROI;
    int p  = i - n * BINS_PER_ROI;
    int ph = p / OUT_;
    int pw = p - ph * OUT_;

    const float* r = rois + n * 5;
    int   b   = (int)r[0];
    float sx1 = r[1] * SCALE_;
    float sy1 = r[2] * SCALE_;
    float sx2 = r[3] * SCALE_;
    float sy2 = r[4] * SCALE_;

    float rw = fmaxf(sx2 - sx1, 1.0f);   // aligned=False -> clamp to 1
    float rh = fmaxf(sy2 - sy1, 1.0f);
    float bin_w = rw * (1.0f / OUT_);
    float bin_h = rh * (1.0f / OUT_);

    // sampling_ratio = 1: single sample at bin center
    float x = sx1 + ((float)pw + 0.5f) * bin_w;
    float y = sy1 + ((float)ph + 0.5f) * bin_h;

    float valid = (y > -1.0f && y < (float)H_ && x > -1.0f && x < (float)W_)
                      ? 1.0f : 0.0f;

    y = fminf(fmaxf(y, 0.0f), (float)(H_ - 1));
    x = fminf(fmaxf(x, 0.0f), (float)(W_ - 1));

    int   y0 = (int)floorf(y);
    int   x0 = (int)floorf(x);
    float ly = y - (float)y0;
    float lx = x - (float)x0;

    // Edge re-parameterization: keep (y0+1, x0+1) taps in-bounds.
    if (y0 >= H_ - 1) { y0 = H_ - 2; ly = 1.0f; }
    if (x0 >= W_ - 1) { x0 = W_ - 2; lx = 1.0f; }

    float hy = 1.0f - ly;
    float hx = 1.0f - lx;

    g_off[i] = b * CHW_ + y0 * W_ + x0;
    g_w[i]   = make_float4(hy * hx * valid,
                           hy * lx * valid,
                           ly * hx * valid,
                           ly * lx * valid);
}

// ---------------------------------------------------------------------------
// Phase 2: one block = (batch-sorted roi slot, 64-channel group).
// 196 threads = 4 subgroups x 49 bins. Each thread owns ONE bin: metadata
// (offset + float4 weights) loads once into registers, then 16 channels are
// processed with 4 scalar taps + 1 coalesced store each. No shared memory,
// no syncs. Scalar taps are deliberate: 32-lane scalar LDG = 1 wavefront
// per distinct 128B line, whereas wide loads need >=4 wavefronts regardless
// (measured regressions R8/R15). Lanes span consecutive bins at a fixed
// channel — the minimal-distinct-lines warp layout.
// ---------------------------------------------------------------------------
__global__ __launch_bounds__(GATHER_THREADS)
void roi_gather_kernel(const float* __restrict__ feat,
                       float* __restrict__ out) {
    int slot = blockIdx.x >> 2;          // / NCG_ (4)
    int cg   = blockIdx.x & (NCG_ - 1);
    int n    = g_order[slot];
    int c0   = cg * CG_;

    int t = threadIdx.x;
    int g = t / BINS_PER_ROI;            // 0..3
    int p = t - g * BINS_PER_ROI;        // 0..48

    int bin = n * BINS_PER_ROI + p;
    int    off_base = g_off[bin] + (c0 + g * CH_PER_THREAD) * HW_;
    float4 w        = g_w[bin];

    float* out_base = out + (n * C_ + c0 + g * CH_PER_THREAD) * BINS_PER_ROI + p;

    #pragma unroll
    for (int i = 0; i < CH_PER_THREAD; i++) {
        const float* ptr = feat + off_base + i * HW_;
        float f00 = __ldg(ptr);
        float f01 = __ldg(ptr + 1);
        float f10 = __ldg(ptr + W_);
        float f11 = __ldg(ptr + W_ + 1);

        out_base[i * BINS_PER_ROI] =
            f00 * w.x + f01 * w.y + f10 * w.z + f11 * w.w;
    }
}

// ---------------------------------------------------------------------------
extern "C" void kernel_launch(void* const* d_in, const int* in_sizes, int n_in,
                              void* d_out, int out_size) {
    const float* feat = (const float*)d_in[0];
    const float* rois = (const float*)d_in[1];
    float* out = (float*)d_out;

    int N = in_sizes[1] / 5;
    int n_bins = N * BINS_PER_ROI;
    int prep_blocks = (n_bins + 255) / 256;

    roi_prep_sort_kernel<<<prep_blocks + 1, 256>>>(rois, n_bins, N);
    roi_gather_kernel<<<N * NCG_, GATHER_THREADS>>>(feat, out);
}